// round 10
// baseline (speedup 1.0000x reference)
#include <cuda_runtime.h>
#include <cuda_fp16.h>
#include <cstdint>

// LSTM discriminator: B=2048, T=512, H=128.
// 128 CTAs x 256 threads (8 warps, 2/SMSP); warp w owns j in [16w,16w+16)
// of each gate (two n8 tiles). Halves per-step SMEM A-traffic vs 16 warps.
// f16-accumulator HMMA, tanh.approx.f16x2, 0.5 folded into W/b for i,f,o.
// All 8 ldmatrix.x4 preloaded at step start; kk-outer MMA order (8 chains).

#define T_STEPS 512
#define HDIM    128
#define MB      16
#define HSTR    136   // padded stride in halves (272B): LDSM + STS conflict-free

__device__ __forceinline__ __half2 tanh2(__half2 x) {
    uint32_t xi = *reinterpret_cast<uint32_t*>(&x), yi;
    asm("tanh.approx.f16x2 %0, %1;" : "=r"(yi) : "r"(xi));
    return *reinterpret_cast<__half2*>(&yi);
}

__device__ __forceinline__ void mma16816_f16(uint32_t d[2], const uint32_t a[4],
                                             const uint32_t b[2]) {
    asm volatile(
        "mma.sync.aligned.m16n8k16.row.col.f16.f16.f16.f16 "
        "{%0,%1}, {%2,%3,%4,%5}, {%6,%7}, {%0,%1};\n"
        : "+r"(d[0]), "+r"(d[1])
        : "r"(a[0]), "r"(a[1]), "r"(a[2]), "r"(a[3]), "r"(b[0]), "r"(b[1]));
}

__device__ __forceinline__ void ldsm_x4(uint32_t a[4], uint32_t saddr) {
    asm volatile(
        "ldmatrix.sync.aligned.m8n8.x4.shared.b16 {%0,%1,%2,%3}, [%4];"
        : "=r"(a[0]), "=r"(a[1]), "=r"(a[2]), "=r"(a[3])
        : "r"(saddr));
}

__global__ __launch_bounds__(256, 1)
void lstm_disc_kernel(
    const float* __restrict__ x,      // [B, T]
    const float* __restrict__ hx0,    // [B, H]
    const float* __restrict__ cx0,    // [B, H]
    const float* __restrict__ W_ih,   // [4H, 1]
    const float* __restrict__ W_hh,   // [4H, H]
    const float* __restrict__ b_ih,   // [4H]
    const float* __restrict__ b_hh,   // [4H]
    const float* __restrict__ W_mlp,  // [1, H]
    const float* __restrict__ b_mlp,  // [1]
    float* __restrict__ out)          // [B, 1]
{
    __shared__ float xs[MB][T_STEPS + 1];
    __shared__ __align__(16) __half hbuf[2][MB][HSTR];
    __shared__ __half2 wih2[4][64];   // W_ih pairs (pre-halved for i,f,o)
    __shared__ __half2 bb2[4][64];    // b_ih+b_hh pairs (pre-halved for i,f,o)

    const int tid  = threadIdx.x;
    const int w    = tid >> 5;   // warp 0..7: owns j in [16w, 16w+16) of each gate
    const int l    = tid & 31;
    const int qr   = l >> 2;     // 0..7
    const int ql   = l & 3;      // 0..3
    const int brow = blockIdx.x * MB;

    // ---- one-time loads ----
    for (int i = tid; i < MB * T_STEPS; i += 256)
        xs[i / T_STEPS][i % T_STEPS] = x[(size_t)(brow + i / T_STEPS) * T_STEPS + (i % T_STEPS)];
    for (int i = tid; i < 4 * 64; i += 256) {
        int g = i >> 6, p = i & 63, j = 2 * p;
        float sc = (g == 2) ? 1.0f : 0.5f;
        wih2[g][p] = __floats2half2_rn(sc * W_ih[g * HDIM + j], sc * W_ih[g * HDIM + j + 1]);
        bb2[g][p]  = __floats2half2_rn(sc * (b_ih[g * HDIM + j] + b_hh[g * HDIM + j]),
                                       sc * (b_ih[g * HDIM + j + 1] + b_hh[g * HDIM + j + 1]));
    }
    for (int i = tid; i < MB * HDIM; i += 256) {
        int r = i / HDIM, j = i % HDIM;
        hbuf[0][r][j] = __float2half(hx0[(size_t)(brow + r) * HDIM + j]);
    }

    // W_hh -> f16 B fragments (pre-halved for i,f,o). 128 regs.
    // Bf[g][t2][kk]: n = g*128 + 16w + 8*t2 + qr, k = 16kk + 2ql (+8)
    uint32_t Bf[4][2][8][2];
    #pragma unroll
    for (int g = 0; g < 4; ++g) {
        float sc = (g == 2) ? 1.0f : 0.5f;
        #pragma unroll
        for (int t2 = 0; t2 < 2; ++t2)
            #pragma unroll
            for (int kk = 0; kk < 8; ++kk) {
                int n = g * HDIM + w * 16 + t2 * 8 + qr;
                int k = kk * 16 + 2 * ql;
                float2 v0 = *reinterpret_cast<const float2*>(&W_hh[(size_t)n * HDIM + k]);
                float2 v1 = *reinterpret_cast<const float2*>(&W_hh[(size_t)n * HDIM + k + 8]);
                __half2 h0 = __floats2half2_rn(sc * v0.x, sc * v0.y);
                __half2 h1 = __floats2half2_rn(sc * v1.x, sc * v1.y);
                Bf[g][t2][kk][0] = *reinterpret_cast<uint32_t*>(&h0);
                Bf[g][t2][kk][1] = *reinterpret_cast<uint32_t*>(&h1);
            }
    }

    // per-thread input-weight / bias pairs; j-pair index = 8w + 4t2 + ql
    __half2 wi2[4][2], bi2[4][2];
    __syncthreads();
    #pragma unroll
    for (int g = 0; g < 4; ++g)
        #pragma unroll
        for (int t2 = 0; t2 < 2; ++t2) {
            int jp = w * 8 + t2 * 4 + ql;
            wi2[g][t2] = wih2[g][jp];
            bi2[g][t2] = bb2[g][jp];
        }

    // cell state: cst[t2][rr] covers (row qr+8rr, j = 16w+8t2+2ql+{0,1})
    __half2 cst[2][2];
    #pragma unroll
    for (int t2 = 0; t2 < 2; ++t2)
        #pragma unroll
        for (int rr = 0; rr < 2; ++rr) {
            int r = brow + qr + 8 * rr;
            int j = w * 16 + t2 * 8 + 2 * ql;
            cst[t2][rr] = __floats2half2_rn(cx0[(size_t)r * HDIM + j],
                                            cx0[(size_t)r * HDIM + j + 1]);
        }

    const int lrow = l & 15;
    const int lkof = (l >> 4) * 8;
    const __half2 h05 = __float2half2_rn(0.5f);

    // ---- recurrence ----
    #pragma unroll 1
    for (int t = 0; t < T_STEPS; ++t) {
        const int rb = t & 1, wbuf = rb ^ 1;

        // preload ALL A fragments: 8 x ldmatrix.x4 back-to-back (32 regs)
        uint32_t A[8][4];
        #pragma unroll
        for (int kk = 0; kk < 8; ++kk)
            ldsm_x4(A[kk], (uint32_t)__cvta_generic_to_shared(
                &hbuf[rb][lrow][kk * 16 + lkof]));

        uint32_t acc[4][2][2];
        #pragma unroll
        for (int g = 0; g < 4; ++g)
            #pragma unroll
            for (int t2 = 0; t2 < 2; ++t2) { acc[g][t2][0] = 0u; acc[g][t2][1] = 0u; }

        // 64 HMMA, kk-outer: 8 independent chains, reuse spacing = 8 issues
        #pragma unroll
        for (int kk = 0; kk < 8; ++kk)
            #pragma unroll
            for (int g = 0; g < 4; ++g)
                #pragma unroll
                for (int t2 = 0; t2 < 2; ++t2)
                    mma16816_f16(acc[g][t2], A[kk], Bf[g][t2][kk]);

        // epilogue (f16x2): 16 tanh2 per thread
        __half2 xr2[2] = { __float2half2_rn(xs[qr][t]),
                           __float2half2_rn(xs[qr + 8][t]) };
        #pragma unroll
        for (int t2 = 0; t2 < 2; ++t2) {
            #pragma unroll
            for (int rr = 0; rr < 2; ++rr) {
                __half2 gi = __hadd2(*reinterpret_cast<__half2*>(&acc[0][t2][rr]),
                                     __hfma2(xr2[rr], wi2[0][t2], bi2[0][t2]));
                __half2 gf = __hadd2(*reinterpret_cast<__half2*>(&acc[1][t2][rr]),
                                     __hfma2(xr2[rr], wi2[1][t2], bi2[1][t2]));
                __half2 gg = __hadd2(*reinterpret_cast<__half2*>(&acc[2][t2][rr]),
                                     __hfma2(xr2[rr], wi2[2][t2], bi2[2][t2]));
                __half2 go = __hadd2(*reinterpret_cast<__half2*>(&acc[3][t2][rr]),
                                     __hfma2(xr2[rr], wi2[3][t2], bi2[3][t2]));
                __half2 iv = __hfma2(tanh2(gi), h05, h05);
                __half2 fv = __hfma2(tanh2(gf), h05, h05);
                __half2 gv = tanh2(gg);
                __half2 ov = __hfma2(tanh2(go), h05, h05);
                __half2 c  = __hfma2(fv, cst[t2][rr], __hmul2(iv, gv));
                cst[t2][rr] = c;
                __half2 hv = __hmul2(ov, tanh2(c));
                *reinterpret_cast<uint32_t*>(
                    &hbuf[wbuf][qr + 8 * rr][w * 16 + t2 * 8 + 2 * ql]) =
                    *reinterpret_cast<uint32_t*>(&hv);
            }
        }
        __syncthreads();
    }

    // ---- final MLP + sigmoid ----  (h(T) in hbuf[0], T even)
    if (tid < 128) {
        int r = tid >> 3, q = tid & 7;
        float s = 0.f;
        #pragma unroll
        for (int k = 0; k < 16; ++k) {
            int j = q * 16 + k;
            s = fmaf(__half2float(hbuf[0][r][j]), W_mlp[j], s);
        }
        s += __shfl_xor_sync(0xffffffffu, s, 1);
        s += __shfl_xor_sync(0xffffffffu, s, 2);
        s += __shfl_xor_sync(0xffffffffu, s, 4);
        if (q == 0) {
            float z = s + b_mlp[0];
            out[brow + r] = 1.f / (1.f + __expf(-z));
        }
    }
}

extern "C" void kernel_launch(void* const* d_in, const int* in_sizes, int n_in,
                              void* d_out, int out_size) {
    const float* x     = (const float*)d_in[0];
    const float* hx0   = (const float*)d_in[1];
    const float* cx0   = (const float*)d_in[2];
    const float* W_ih  = (const float*)d_in[3];
    const float* W_hh  = (const float*)d_in[4];
    const float* b_ih  = (const float*)d_in[5];
    const float* b_hh  = (const float*)d_in[6];
    const float* W_mlp = (const float*)d_in[7];
    const float* b_mlp = (const float*)d_in[8];
    float* out = (float*)d_out;

    const int B = out_size;          // 2048
    dim3 grid(B / MB), block(256);
    lstm_disc_kernel<<<grid, block>>>(x, hx0, cx0, W_ih, W_hh, b_ih, b_hh,
                                      W_mlp, b_mlp, out);
}

// round 13
// speedup vs baseline: 1.1358x; 1.1358x over previous
#include <cuda_runtime.h>
#include <cuda_fp16.h>
#include <cstdint>

// LSTM discriminator: B=2048, T=512, H=128.
// 128 CTAs x 512 threads (16 warps, 4/SMSP); warp w owns j in [8w,8w+8).
// f16-accumulator HMMA; tanh.approx.f16x2; 0.5 folded into W/b for i,f,o.
// NEW vs best (R5): (a) x/bias contribution pre-loaded INTO the MMA
// accumulator (no post-MMA hadd2), (b) next step's pre computed before the
// barrier (post-barrier head = LDSM+MMA only), (c) loop-invariant addresses.

#define T_STEPS 512
#define HDIM    128
#define MB      16
#define HSTR    136   // padded stride in halves (272B): LDSM + STS conflict-free

__device__ __forceinline__ __half2 tanh2(__half2 x) {
    uint32_t xi = *reinterpret_cast<uint32_t*>(&x), yi;
    asm("tanh.approx.f16x2 %0, %1;" : "=r"(yi) : "r"(xi));
    return *reinterpret_cast<__half2*>(&yi);
}

__device__ __forceinline__ void mma16816_f16(uint32_t d[2], const uint32_t a[4],
                                             const uint32_t b[2]) {
    asm volatile(
        "mma.sync.aligned.m16n8k16.row.col.f16.f16.f16.f16 "
        "{%0,%1}, {%2,%3,%4,%5}, {%6,%7}, {%0,%1};\n"
        : "+r"(d[0]), "+r"(d[1])
        : "r"(a[0]), "r"(a[1]), "r"(a[2]), "r"(a[3]), "r"(b[0]), "r"(b[1]));
}

__device__ __forceinline__ void ldsm_x4(uint32_t a[4], uint32_t saddr) {
    asm volatile(
        "ldmatrix.sync.aligned.m8n8.x4.shared.b16 {%0,%1,%2,%3}, [%4];"
        : "=r"(a[0]), "=r"(a[1]), "=r"(a[2]), "=r"(a[3])
        : "r"(saddr));
}

__global__ __launch_bounds__(512, 1)
void lstm_disc_kernel(
    const float* __restrict__ x,      // [B, T]
    const float* __restrict__ hx0,    // [B, H]
    const float* __restrict__ cx0,    // [B, H]
    const float* __restrict__ W_ih,   // [4H, 1]
    const float* __restrict__ W_hh,   // [4H, H]
    const float* __restrict__ b_ih,   // [4H]
    const float* __restrict__ b_hh,   // [4H]
    const float* __restrict__ W_mlp,  // [1, H]
    const float* __restrict__ b_mlp,  // [1]
    float* __restrict__ out)          // [B, 1]
{
    __shared__ float xs[MB][T_STEPS + 1];   // col T_STEPS = pad (prefetch target)
    __shared__ __align__(16) __half hbuf[2][MB][HSTR];
    __shared__ __half2 wih2[4][64];   // W_ih pairs (pre-halved for i,f,o)
    __shared__ __half2 bb2[4][64];    // b_ih+b_hh pairs (pre-halved for i,f,o)

    const int tid  = threadIdx.x;
    const int w    = tid >> 5;   // warp 0..15
    const int l    = tid & 31;
    const int qr   = l >> 2;     // 0..7
    const int ql   = l & 3;      // 0..3
    const int brow = blockIdx.x * MB;

    // ---- one-time loads ----
    for (int i = tid; i < MB * T_STEPS; i += 512)
        xs[i / T_STEPS][i % T_STEPS] = x[(size_t)(brow + i / T_STEPS) * T_STEPS + (i % T_STEPS)];
    if (tid < MB) xs[tid][T_STEPS] = 0.f;   // pad column for last prefetch
    for (int i = tid; i < 4 * 64; i += 512) {
        int g = i >> 6, p = i & 63, j = 2 * p;
        float sc = (g == 2) ? 1.0f : 0.5f;
        wih2[g][p] = __floats2half2_rn(sc * W_ih[g * HDIM + j], sc * W_ih[g * HDIM + j + 1]);
        bb2[g][p]  = __floats2half2_rn(sc * (b_ih[g * HDIM + j] + b_hh[g * HDIM + j]),
                                       sc * (b_ih[g * HDIM + j + 1] + b_hh[g * HDIM + j + 1]));
    }
    for (int i = tid; i < MB * HDIM; i += 512) {
        int r = i / HDIM, j = i % HDIM;
        hbuf[0][r][j] = __float2half(hx0[(size_t)(brow + r) * HDIM + j]);
    }

    // W_hh -> f16 B fragments in registers (pre-halved for gates i,f,o).
    uint32_t Bf[4][8][2];
    #pragma unroll
    for (int g = 0; g < 4; ++g) {
        float sc = (g == 2) ? 1.0f : 0.5f;
        #pragma unroll
        for (int kk = 0; kk < 8; ++kk) {
            int n = g * HDIM + w * 8 + qr;
            int k = kk * 16 + 2 * ql;
            float2 v0 = *reinterpret_cast<const float2*>(&W_hh[(size_t)n * HDIM + k]);
            float2 v1 = *reinterpret_cast<const float2*>(&W_hh[(size_t)n * HDIM + k + 8]);
            __half2 h0 = __floats2half2_rn(sc * v0.x, sc * v0.y);
            __half2 h1 = __floats2half2_rn(sc * v1.x, sc * v1.y);
            Bf[g][kk][0] = *reinterpret_cast<uint32_t*>(&h0);
            Bf[g][kk][1] = *reinterpret_cast<uint32_t*>(&h1);
        }
    }

    const int jp = w * 4 + ql;
    __half2 wi2[4], bi2[4];
    __syncthreads();
    #pragma unroll
    for (int g = 0; g < 4; ++g) { wi2[g] = wih2[g][jp]; bi2[g] = bb2[g][jp]; }

    __half2 cst[2];
    #pragma unroll
    for (int rr = 0; rr < 2; ++rr) {
        int r = brow + qr + 8 * rr;
        int j = w * 8 + 2 * ql;
        cst[rr] = __floats2half2_rn(cx0[(size_t)r * HDIM + j],
                                    cx0[(size_t)r * HDIM + j + 1]);
    }

    const int lrow = l & 15;
    const int lkof = (l >> 4) * 8;
    const __half2 h05 = __float2half2_rn(0.5f);

    // loop-invariant LDSM base addresses (per buffer) and STS addresses
    uint32_t abase[2];
    abase[0] = (uint32_t)__cvta_generic_to_shared(&hbuf[0][lrow][lkof]);
    abase[1] = (uint32_t)__cvta_generic_to_shared(&hbuf[1][lrow][lkof]);
    uint32_t* sts0[2];
    sts0[0] = reinterpret_cast<uint32_t*>(&hbuf[0][qr][w * 8 + 2 * ql]);
    sts0[1] = reinterpret_cast<uint32_t*>(&hbuf[1][qr][w * 8 + 2 * ql]);

    // pre for t=0 (bias + x contribution), lives in regs across the barrier
    __half2 pre[4][2];
    {
        __half2 x0 = __float2half2_rn(xs[qr][0]);
        __half2 x1 = __float2half2_rn(xs[qr + 8][0]);
        #pragma unroll
        for (int g = 0; g < 4; ++g) {
            pre[g][0] = __hfma2(x0, wi2[g], bi2[g]);
            pre[g][1] = __hfma2(x1, wi2[g], bi2[g]);
        }
    }
    __syncthreads();

    // ---- recurrence ----
    #pragma unroll 1
    for (int t = 0; t < T_STEPS; ++t) {
        const int rb = t & 1, wbuf = rb ^ 1;

        // accumulators initialized with x/bias contribution (no post-MMA add)
        uint32_t acc[4][2];
        #pragma unroll
        for (int g = 0; g < 4; ++g) {
            acc[g][0] = *reinterpret_cast<uint32_t*>(&pre[g][0]);
            acc[g][1] = *reinterpret_cast<uint32_t*>(&pre[g][1]);
        }

        uint32_t A[4][4];
        // first k-half
        #pragma unroll
        for (int kk = 0; kk < 4; ++kk)
            ldsm_x4(A[kk], abase[rb] + kk * 32);          // 16 halves = 32 B
        #pragma unroll
        for (int kk = 0; kk < 4; ++kk)
            #pragma unroll
            for (int g = 0; g < 4; ++g)
                mma16816_f16(acc[g], A[kk], Bf[g][kk]);
        // second k-half
        #pragma unroll
        for (int kk = 0; kk < 4; ++kk)
            ldsm_x4(A[kk], abase[rb] + (kk + 4) * 32);
        #pragma unroll
        for (int kk = 0; kk < 4; ++kk)
            #pragma unroll
            for (int g = 0; g < 4; ++g)
                mma16816_f16(acc[g], A[kk], Bf[g][kk + 4]);

        // epilogue: gates already complete in acc
        #pragma unroll
        for (int rr = 0; rr < 2; ++rr) {
            __half2 iv = __hfma2(tanh2(*reinterpret_cast<__half2*>(&acc[0][rr])), h05, h05);
            __half2 fv = __hfma2(tanh2(*reinterpret_cast<__half2*>(&acc[1][rr])), h05, h05);
            __half2 gv = tanh2(*reinterpret_cast<__half2*>(&acc[2][rr]));
            __half2 ov = __hfma2(tanh2(*reinterpret_cast<__half2*>(&acc[3][rr])), h05, h05);
            __half2 c  = __hfma2(fv, cst[rr], __hmul2(iv, gv));
            cst[rr] = c;
            __half2 hv = __hmul2(ov, tanh2(c));
            sts0[wbuf][rr * 8 * HSTR / 2] = *reinterpret_cast<uint32_t*>(&hv);
        }

        // prefetch next step's pre BEFORE the barrier (off critical path)
        {
            __half2 x0 = __float2half2_rn(xs[qr][t + 1]);
            __half2 x1 = __float2half2_rn(xs[qr + 8][t + 1]);
            #pragma unroll
            for (int g = 0; g < 4; ++g) {
                pre[g][0] = __hfma2(x0, wi2[g], bi2[g]);
                pre[g][1] = __hfma2(x1, wi2[g], bi2[g]);
            }
        }
        __syncthreads();
    }

    // ---- final MLP + sigmoid ----  (h(T) in hbuf[0], T even)
    if (tid < 128) {
        int r = tid >> 3, q = tid & 7;
        float s = 0.f;
        #pragma unroll
        for (int k = 0; k < 16; ++k) {
            int j = q * 16 + k;
            s = fmaf(__half2float(hbuf[0][r][j]), W_mlp[j], s);
        }
        s += __shfl_xor_sync(0xffffffffu, s, 1);
        s += __shfl_xor_sync(0xffffffffu, s, 2);
        s += __shfl_xor_sync(0xffffffffu, s, 4);
        if (q == 0) {
            float z = s + b_mlp[0];
            out[brow + r] = 1.f / (1.f + __expf(-z));
        }
    }
}

extern "C" void kernel_launch(void* const* d_in, const int* in_sizes, int n_in,
                              void* d_out, int out_size) {
    const float* x     = (const float*)d_in[0];
    const float* hx0   = (const float*)d_in[1];
    const float* cx0   = (const float*)d_in[2];
    const float* W_ih  = (const float*)d_in[3];
    const float* W_hh  = (const float*)d_in[4];
    const float* b_ih  = (const float*)d_in[5];
    const float* b_hh  = (const float*)d_in[6];
    const float* W_mlp = (const float*)d_in[7];
    const float* b_mlp = (const float*)d_in[8];
    float* out = (float*)d_out;

    const int B = out_size;          // 2048
    dim3 grid(B / MB), block(512);
    lstm_disc_kernel<<<grid, block>>>(x, hx0, cx0, W_ih, W_hh, b_ih, b_hh,
                                      W_mlp, b_mlp, out);
}

// round 14
// speedup vs baseline: 1.1512x; 1.0135x over previous
#include <cuda_runtime.h>
#include <cuda_fp16.h>
#include <cstdint>

// LSTM discriminator: B=2048, T=512, H=128.
// 128 CTAs x 512 threads (16 warps); warp w owns j in [8w,8w+8) of each gate.
// R13 base (pre folded into acc init, pre(t+1) prefetch, invariant addrs) +
// pinned gate-major second k-half with epilogue MUFU interleaved under MMAs
// (tanh2 is asm volatile so the schedule survives compilation), and LDSM
// ping-pong so the load stream stays ahead of the MMA wave.

#define T_STEPS 512
#define HDIM    128
#define MB      16
#define HSTR    136   // padded stride in halves (272B): LDSM + STS conflict-free

__device__ __forceinline__ __half2 tanh2(__half2 x) {
    uint32_t xi = *reinterpret_cast<uint32_t*>(&x), yi;
    asm volatile("tanh.approx.f16x2 %0, %1;" : "=r"(yi) : "r"(xi));
    return *reinterpret_cast<__half2*>(&yi);
}

__device__ __forceinline__ void mma16816_f16(uint32_t d[2], const uint32_t a[4],
                                             const uint32_t b[2]) {
    asm volatile(
        "mma.sync.aligned.m16n8k16.row.col.f16.f16.f16.f16 "
        "{%0,%1}, {%2,%3,%4,%5}, {%6,%7}, {%0,%1};\n"
        : "+r"(d[0]), "+r"(d[1])
        : "r"(a[0]), "r"(a[1]), "r"(a[2]), "r"(a[3]), "r"(b[0]), "r"(b[1]));
}

__device__ __forceinline__ void ldsm_x4(uint32_t a[4], uint32_t saddr) {
    asm volatile(
        "ldmatrix.sync.aligned.m8n8.x4.shared.b16 {%0,%1,%2,%3}, [%4];"
        : "=r"(a[0]), "=r"(a[1]), "=r"(a[2]), "=r"(a[3])
        : "r"(saddr));
}

__global__ __launch_bounds__(512, 1)
void lstm_disc_kernel(
    const float* __restrict__ x,      // [B, T]
    const float* __restrict__ hx0,    // [B, H]
    const float* __restrict__ cx0,    // [B, H]
    const float* __restrict__ W_ih,   // [4H, 1]
    const float* __restrict__ W_hh,   // [4H, H]
    const float* __restrict__ b_ih,   // [4H]
    const float* __restrict__ b_hh,   // [4H]
    const float* __restrict__ W_mlp,  // [1, H]
    const float* __restrict__ b_mlp,  // [1]
    float* __restrict__ out)          // [B, 1]
{
    __shared__ float xs[MB][T_STEPS + 1];   // col T_STEPS = pad for last prefetch
    __shared__ __align__(16) __half hbuf[2][MB][HSTR];
    __shared__ __half2 wih2[4][64];   // W_ih pairs (pre-halved for i,f,o)
    __shared__ __half2 bb2[4][64];    // b_ih+b_hh pairs (pre-halved for i,f,o)

    const int tid  = threadIdx.x;
    const int w    = tid >> 5;
    const int l    = tid & 31;
    const int qr   = l >> 2;
    const int ql   = l & 3;
    const int brow = blockIdx.x * MB;

    // ---- one-time loads ----
    for (int i = tid; i < MB * T_STEPS; i += 512)
        xs[i / T_STEPS][i % T_STEPS] = x[(size_t)(brow + i / T_STEPS) * T_STEPS + (i % T_STEPS)];
    if (tid < MB) xs[tid][T_STEPS] = 0.f;
    for (int i = tid; i < 4 * 64; i += 512) {
        int g = i >> 6, p = i & 63, j = 2 * p;
        float sc = (g == 2) ? 1.0f : 0.5f;
        wih2[g][p] = __floats2half2_rn(sc * W_ih[g * HDIM + j], sc * W_ih[g * HDIM + j + 1]);
        bb2[g][p]  = __floats2half2_rn(sc * (b_ih[g * HDIM + j] + b_hh[g * HDIM + j]),
                                       sc * (b_ih[g * HDIM + j + 1] + b_hh[g * HDIM + j + 1]));
    }
    for (int i = tid; i < MB * HDIM; i += 512) {
        int r = i / HDIM, j = i % HDIM;
        hbuf[0][r][j] = __float2half(hx0[(size_t)(brow + r) * HDIM + j]);
    }

    // W_hh -> f16 B fragments (pre-halved for i,f,o)
    uint32_t Bf[4][8][2];
    #pragma unroll
    for (int g = 0; g < 4; ++g) {
        float sc = (g == 2) ? 1.0f : 0.5f;
        #pragma unroll
        for (int kk = 0; kk < 8; ++kk) {
            int n = g * HDIM + w * 8 + qr;
            int k = kk * 16 + 2 * ql;
            float2 v0 = *reinterpret_cast<const float2*>(&W_hh[(size_t)n * HDIM + k]);
            float2 v1 = *reinterpret_cast<const float2*>(&W_hh[(size_t)n * HDIM + k + 8]);
            __half2 h0 = __floats2half2_rn(sc * v0.x, sc * v0.y);
            __half2 h1 = __floats2half2_rn(sc * v1.x, sc * v1.y);
            Bf[g][kk][0] = *reinterpret_cast<uint32_t*>(&h0);
            Bf[g][kk][1] = *reinterpret_cast<uint32_t*>(&h1);
        }
    }

    const int jp = w * 4 + ql;
    __half2 wi2[4], bi2[4];
    __syncthreads();
    #pragma unroll
    for (int g = 0; g < 4; ++g) { wi2[g] = wih2[g][jp]; bi2[g] = bb2[g][jp]; }

    __half2 cst[2];
    #pragma unroll
    for (int rr = 0; rr < 2; ++rr) {
        int r = brow + qr + 8 * rr;
        int j = w * 8 + 2 * ql;
        cst[rr] = __floats2half2_rn(cx0[(size_t)r * HDIM + j],
                                    cx0[(size_t)r * HDIM + j + 1]);
    }

    const int lrow = l & 15;
    const int lkof = (l >> 4) * 8;
    const __half2 h05 = __float2half2_rn(0.5f);

    uint32_t abase[2];
    abase[0] = (uint32_t)__cvta_generic_to_shared(&hbuf[0][lrow][lkof]);
    abase[1] = (uint32_t)__cvta_generic_to_shared(&hbuf[1][lrow][lkof]);
    uint32_t* sts0[2];
    sts0[0] = reinterpret_cast<uint32_t*>(&hbuf[0][qr][w * 8 + 2 * ql]);
    sts0[1] = reinterpret_cast<uint32_t*>(&hbuf[1][qr][w * 8 + 2 * ql]);

    // pre for t=0
    __half2 pre[4][2];
    {
        __half2 x0 = __float2half2_rn(xs[qr][0]);
        __half2 x1 = __float2half2_rn(xs[qr + 8][0]);
        #pragma unroll
        for (int g = 0; g < 4; ++g) {
            pre[g][0] = __hfma2(x0, wi2[g], bi2[g]);
            pre[g][1] = __hfma2(x1, wi2[g], bi2[g]);
        }
    }
    __syncthreads();

    // ---- recurrence ----
    #pragma unroll 1
    for (int t = 0; t < T_STEPS; ++t) {
        const int rb = t & 1, wbuf = rb ^ 1;

        uint32_t acc[4][2];
        #pragma unroll
        for (int g = 0; g < 4; ++g) {
            acc[g][0] = *reinterpret_cast<uint32_t*>(&pre[g][0]);
            acc[g][1] = *reinterpret_cast<uint32_t*>(&pre[g][1]);
        }

        uint32_t A[4][4];
        // LDSM kk0-3, then kk-outer MMAs with kk4-7 ping-ponged in behind
        #pragma unroll
        for (int kk = 0; kk < 4; ++kk)
            ldsm_x4(A[kk], abase[rb] + kk * 32);
        #pragma unroll
        for (int kk = 0; kk < 4; ++kk) {
            #pragma unroll
            for (int g = 0; g < 4; ++g)
                mma16816_f16(acc[g], A[kk], Bf[g][kk]);
            ldsm_x4(A[kk], abase[rb] + (kk + 4) * 32);   // reuse tile for kk+4
        }

        // ---- second k-half: gate-major i, g, f, o with pinned epilogue ----
        // gate i
        #pragma unroll
        for (int kk = 0; kk < 4; ++kk)
            mma16816_f16(acc[0], A[kk], Bf[0][kk + 4]);
        // gate g
        #pragma unroll
        for (int kk = 0; kk < 4; ++kk)
            mma16816_f16(acc[2], A[kk], Bf[2][kk + 4]);
        __half2 ti[2];
        #pragma unroll
        for (int rr = 0; rr < 2; ++rr)
            ti[rr] = tanh2(*reinterpret_cast<__half2*>(&acc[0][rr]));   // under g MMAs' drain
        // gate f
        #pragma unroll
        for (int kk = 0; kk < 4; ++kk)
            mma16816_f16(acc[1], A[kk], Bf[1][kk + 4]);
        __half2 ig[2];
        #pragma unroll
        for (int rr = 0; rr < 2; ++rr) {
            __half2 gv = tanh2(*reinterpret_cast<__half2*>(&acc[2][rr]));
            __half2 iv = __hfma2(ti[rr], h05, h05);
            ig[rr] = __hmul2(iv, gv);
        }
        // gate o
        #pragma unroll
        for (int kk = 0; kk < 4; ++kk)
            mma16816_f16(acc[3], A[kk], Bf[3][kk + 4]);
        __half2 tc[2];
        #pragma unroll
        for (int rr = 0; rr < 2; ++rr) {
            __half2 tf = tanh2(*reinterpret_cast<__half2*>(&acc[1][rr]));
            __half2 fv = __hfma2(tf, h05, h05);
            __half2 c  = __hfma2(fv, cst[rr], ig[rr]);
            cst[rr] = c;
            tc[rr] = tanh2(c);
        }

        // pre(t+1) prefetch: fma-pipe work filling the MUFU drain window
        {
            __half2 x0 = __float2half2_rn(xs[qr][t + 1]);
            __half2 x1 = __float2half2_rn(xs[qr + 8][t + 1]);
            #pragma unroll
            for (int g = 0; g < 4; ++g) {
                pre[g][0] = __hfma2(x0, wi2[g], bi2[g]);
                pre[g][1] = __hfma2(x1, wi2[g], bi2[g]);
            }
        }

        // tail: only o-dependent ops remain
        #pragma unroll
        for (int rr = 0; rr < 2; ++rr) {
            __half2 to = tanh2(*reinterpret_cast<__half2*>(&acc[3][rr]));
            __half2 ov = __hfma2(to, h05, h05);
            __half2 hv = __hmul2(ov, tc[rr]);
            sts0[wbuf][rr * 8 * HSTR / 2] = *reinterpret_cast<uint32_t*>(&hv);
        }
        __syncthreads();
    }

    // ---- final MLP + sigmoid ----  (h(T) in hbuf[0], T even)
    if (tid < 128) {
        int r = tid >> 3, q = tid & 7;
        float s = 0.f;
        #pragma unroll
        for (int k = 0; k < 16; ++k) {
            int j = q * 16 + k;
            s = fmaf(__half2float(hbuf[0][r][j]), W_mlp[j], s);
        }
        s += __shfl_xor_sync(0xffffffffu, s, 1);
        s += __shfl_xor_sync(0xffffffffu, s, 2);
        s += __shfl_xor_sync(0xffffffffu, s, 4);
        if (q == 0) {
            float z = s + b_mlp[0];
            out[brow + r] = 1.f / (1.f + __expf(-z));
        }
    }
}

extern "C" void kernel_launch(void* const* d_in, const int* in_sizes, int n_in,
                              void* d_out, int out_size) {
    const float* x     = (const float*)d_in[0];
    const float* hx0   = (const float*)d_in[1];
    const float* cx0   = (const float*)d_in[2];
    const float* W_ih  = (const float*)d_in[3];
    const float* W_hh  = (const float*)d_in[4];
    const float* b_ih  = (const float*)d_in[5];
    const float* b_hh  = (const float*)d_in[6];
    const float* W_mlp = (const float*)d_in[7];
    const float* b_mlp = (const float*)d_in[8];
    float* out = (float*)d_out;

    const int B = out_size;          // 2048
    dim3 grid(B / MB), block(512);
    lstm_disc_kernel<<<grid, block>>>(x, hx0, cx0, W_ih, W_hh, b_ih, b_hh,
                                      W_mlp, b_mlp, out);
}